// round 12
// baseline (speedup 1.0000x reference)
#include <cuda_runtime.h>
#include <cuda_bf16.h>
#include <math.h>
#include <stdint.h>

#define Bc 8
#define Nc 1024
#define Mc 1024
#define Dc 1024
#define Hc 128
#define MBITS 32
#define NEG_INF __int_as_float(0xff800000)

static constexpr float kScale = 0.17677669529663687f; // 1/sqrt(32)
static constexpr float kFixTh = 3e-4f;                // split-GEMM err ~1e-5 rms

// ---------------- scratch (no allocations allowed) ----------------
__device__ float    g_qt[Bc * Nc * MBITS];
__device__ float    g_qr[Bc * Nc * MBITS];
__device__ unsigned g_qb[Bc * Nc];
__device__ float    g_kt[Bc * Mc * MBITS];
__device__ float    g_kr[Bc * Mc * MBITS];
__device__ unsigned g_kb[Bc * Mc];
__device__ float    g_wqT[96 * 1024];   // fp32 transposed weights (fixup path)
__device__ float    g_wkT[96 * 1024];
__device__ __nv_bfloat16 g_wqTh[96 * 1024], g_wqTl[96 * 1024];
__device__ __nv_bfloat16 g_wkTh[96 * 1024], g_wkTl[96 * 1024];
__device__ __nv_bfloat16 g_wvTh[128 * 1024], g_wvTl[128 * 1024];
__device__ __nv_bfloat16 g_vpTh[Bc * 128 * 1024], g_vpTl[Bc * 128 * 1024];

// ================================================================
// helpers
// ================================================================
__device__ __forceinline__ uint32_t smem_u32(const void* p) {
    return (uint32_t)__cvta_generic_to_shared(p);
}
__device__ __forceinline__ void ldsm_x4(uint32_t* r, uint32_t addr) {
    asm volatile("ldmatrix.sync.aligned.m8n8.x4.shared.b16 {%0,%1,%2,%3}, [%4];"
        : "=r"(r[0]), "=r"(r[1]), "=r"(r[2]), "=r"(r[3]) : "r"(addr));
}
__device__ __forceinline__ void mma16816(float* c, const uint32_t* a, const uint32_t* b) {
    asm volatile("mma.sync.aligned.m16n8k16.row.col.f32.bf16.bf16.f32 "
        "{%0,%1,%2,%3}, {%4,%5,%6,%7}, {%8,%9}, {%0,%1,%2,%3};"
        : "+f"(c[0]), "+f"(c[1]), "+f"(c[2]), "+f"(c[3])
        : "r"(a[0]), "r"(a[1]), "r"(a[2]), "r"(a[3]), "r"(b[0]), "r"(b[1]));
}
#define CPA16(dst, src) \
    asm volatile("cp.async.cg.shared.global [%0], [%1], 16;" :: "r"(dst), "l"(src))
#define CP_COMMIT() asm volatile("cp.async.commit_group;" ::: "memory")
#define CP_WAIT1()  asm volatile("cp.async.wait_group 1;" ::: "memory")
#define CP_WAIT0()  asm volatile("cp.async.wait_group 0;" ::: "memory")

__device__ __forceinline__ void split_pack(float4 v, uint2& H, uint2& L) {
    __nv_bfloat16 h0 = __float2bfloat16(v.x), h1 = __float2bfloat16(v.y);
    __nv_bfloat16 h2 = __float2bfloat16(v.z), h3 = __float2bfloat16(v.w);
    __nv_bfloat16 l0 = __float2bfloat16(v.x - __bfloat162float(h0));
    __nv_bfloat16 l1 = __float2bfloat16(v.y - __bfloat162float(h1));
    __nv_bfloat16 l2 = __float2bfloat16(v.z - __bfloat162float(h2));
    __nv_bfloat16 l3 = __float2bfloat16(v.w - __bfloat162float(h3));
    H.x = ((uint32_t)__bfloat16_as_ushort(h1) << 16) | __bfloat16_as_ushort(h0);
    H.y = ((uint32_t)__bfloat16_as_ushort(h3) << 16) | __bfloat16_as_ushort(h2);
    L.x = ((uint32_t)__bfloat16_as_ushort(l1) << 16) | __bfloat16_as_ushort(l0);
    L.y = ((uint32_t)__bfloat16_as_ushort(l3) << 16) | __bfloat16_as_ushort(l2);
}

// packed f32x2 math (sm_100+ PTX)
__device__ __forceinline__ unsigned long long bcast2(float x) {
    unsigned long long r; unsigned xi = __float_as_uint(x);
    asm("mov.b64 %0, {%1, %1};" : "=l"(r) : "r"(xi));
    return r;
}
__device__ __forceinline__ unsigned long long add2(unsigned long long a, unsigned long long b) {
    unsigned long long r;
    asm("add.rn.f32x2 %0, %1, %2;" : "=l"(r) : "l"(a), "l"(b));
    return r;
}
__device__ __forceinline__ void fma2(unsigned long long& d, unsigned long long a, unsigned long long b) {
    asm("fma.rn.f32x2 %0, %1, %2, %0;" : "+l"(d) : "l"(a), "l"(b));
}
__device__ __forceinline__ float2 unpack2(unsigned long long v) {
    unsigned lo, hi;
    asm("mov.b64 {%0, %1}, %2;" : "=r"(lo), "=r"(hi) : "l"(v));
    return make_float2(__uint_as_float(lo), __uint_as_float(hi));
}

// ================================================================
// Split-bf16 HMMA GEMM (R9-proven config): 512 threads = 16 warps,
// 3-stage cp.async, K-chunk 64 (16 chunks), ONE sync/chunk.
// ================================================================
template<int NCOLS, int EPI, int MW, int ASPLIT>
__global__ __launch_bounds__(512, 1) void lgemm_kernel(
    const float* __restrict__ aF0,
    const __nv_bfloat16* __restrict__ aH0, const __nv_bfloat16* __restrict__ aL0,
    const __nv_bfloat16* __restrict__ bH0, const __nv_bfloat16* __restrict__ bL0,
    const float* __restrict__ Bfix0,
    float* __restrict__ p0, float* __restrict__ p1, unsigned* __restrict__ p2,
    const float* __restrict__ aF1,
    const __nv_bfloat16* __restrict__ bH1, const __nv_bfloat16* __restrict__ bL1,
    const float* __restrict__ Bfix1,
    float* __restrict__ q0, float* __restrict__ q1, unsigned* __restrict__ q2,
    int tilesPerSide, int batchB)
{
    extern __shared__ char smem[];
    constexpr int NW   = 16 / MW;
    constexpr int ROWS = MW * 16;
    constexpr int W    = NCOLS / NW;
    constexpr int P    = W / 16;
    constexpr int SKP  = 72;
    constexpr int AB   = ROWS * 144;
    constexpr int BB   = NCOLS * 144;
    constexpr int STG  = 2 * AB + 2 * BB;
    constexpr int ALD  = (ROWS * 16) / 512;
    constexpr int ACP  = (ROWS * 8 + 511) / 512;
    constexpr int BCP  = (NCOLS * 8 + 511) / 512;
    constexpr int ST   = NCOLS + 4;

    const int tid = threadIdx.x;
    const int wid = tid >> 5, lid = tid & 31;
    const int warpM = wid % MW, warpN = wid / MW;

    const float* aF = aF0;
    const __nv_bfloat16 *aH = aH0, *aL = aL0, *bH = bH0, *bL = bL0;
    const float* Bfix = Bfix0;
    float* po0 = p0; float* po1 = p1; unsigned* po2 = p2;
    int row0 = blockIdx.x * ROWS;
    if (EPI == 1 && blockIdx.x >= tilesPerSide) {
        row0 = (blockIdx.x - tilesPerSide) * ROWS;
        aF = aF1; bH = bH1; bL = bL1; Bfix = Bfix1;
        po0 = q0; po1 = q1; po2 = q2;
    }
    size_t bBase = 0;
    if (batchB) bBase = (size_t)(row0 >> 10) * NCOLS * 1024;

    const uint32_t sb = smem_u32(smem);

    auto issueB = [&](int kc, int st) {
        const uint32_t base = sb + st * STG + 2 * AB;
        const int kof = kc * 64;
#pragma unroll
        for (int i = 0; i < BCP; i++) {
            int idx = i * 512 + tid;
            if ((NCOLS * 8) % 512 == 0 || idx < NCOLS * 8) {
                int r = idx >> 3, c = idx & 7;
                size_t so = bBase + (size_t)r * 1024 + kof + c * 8;
                uint32_t dof = base + r * 144 + c * 16;
                CPA16(dof, bH + so);
                CPA16(dof + BB, bL + so);
            }
        }
    };
    auto issueA = [&](int kc, int st) {
        const uint32_t base = sb + st * STG;
        const int kof = kc * 64;
#pragma unroll
        for (int i = 0; i < ACP; i++) {
            int idx = i * 512 + tid;
            if ((ROWS * 8) % 512 == 0 || idx < ROWS * 8) {
                int r = idx >> 3, c = idx & 7;
                size_t so = (size_t)(row0 + r) * 1024 + kof + c * 8;
                uint32_t dof = base + r * 144 + c * 16;
                CPA16(dof, aH + so);
                CPA16(dof + AB, aL + so);
            }
        }
    };
    float4 av[ASPLIT ? ALD : 1];
    auto loadA = [&](int kc) {
#pragma unroll
        for (int i = 0; i < ALD; i++) {
            int idx = i * 512 + tid; int r = idx >> 4, c4 = idx & 15;
            av[i] = *(const float4*)(aF + (size_t)(row0 + r) * 1024 + kc * 64 + c4 * 4);
        }
    };
    auto storeA = [&](int st) {
        char* base = smem + st * STG;
#pragma unroll
        for (int i = 0; i < ALD; i++) {
            int idx = i * 512 + tid; int r = idx >> 4, c4 = idx & 15;
            int off = r * 144 + c4 * 8;
            uint2 H, L; split_pack(av[i], H, L);
            *(uint2*)(base + off) = H;
            *(uint2*)(base + AB + off) = L;
        }
    };

    float acc[P][2][4];
#pragma unroll
    for (int p = 0; p < P; p++)
#pragma unroll
        for (int s = 0; s < 2; s++)
#pragma unroll
            for (int e = 0; e < 4; e++) acc[p][s][e] = 0.f;

    const int aRowB = warpM * 16 + (lid & 15);
    const int aKoff = (lid >> 4) << 3;
    const int bRowB = warpN * W + (lid & 7) + ((lid & 16) >> 1);
    const int bKoff = (lid & 8);

    if (ASPLIT) loadA(0);
    else        issueA(0, 0);
    issueB(0, 0); CP_COMMIT();
    if (!ASPLIT) issueA(1, 1);
    issueB(1, 1); CP_COMMIT();

    int st = 0;
    for (int kc = 0; kc < 16; kc++) {
        if (ASPLIT) {
            storeA(st);
            if (kc < 15) loadA(kc + 1);
        }
        if (kc < 15) CP_WAIT1(); else CP_WAIT0();
        __syncthreads();

        if (kc + 2 < 16) {
            int st2 = st + 2; if (st2 >= 3) st2 -= 3;
            if (!ASPLIT) issueA(kc + 2, st2);
            issueB(kc + 2, st2);
            CP_COMMIT();
        }

        const uint32_t base = sb + st * STG;
#pragma unroll
        for (int ks = 0; ks < 4; ks++) {
            uint32_t ah[4], al[4];
            uint32_t aAddr = base + (uint32_t)(aRowB * SKP + ks * 16 + aKoff) * 2;
            ldsm_x4(ah, aAddr);
            ldsm_x4(al, aAddr + AB);
#pragma unroll
            for (int p = 0; p < P; p++) {
                uint32_t bh[4], bl[4];
                uint32_t bAddr = base + 2 * AB +
                    (uint32_t)((bRowB + p * 16) * SKP + ks * 16 + bKoff) * 2;
                ldsm_x4(bh, bAddr);
                ldsm_x4(bl, bAddr + BB);
                mma16816(acc[p][0], ah, &bh[0]);
                mma16816(acc[p][1], ah, &bh[2]);
                mma16816(acc[p][0], ah, &bl[0]);
                mma16816(acc[p][1], ah, &bl[2]);
                mma16816(acc[p][0], al, &bh[0]);
                mma16816(acc[p][1], al, &bh[2]);
            }
        }
        if (++st == 3) st = 0;
    }
    __syncthreads();

    // ---- stage C to smem ----
    float* stage = (float*)smem;
#pragma unroll
    for (int p = 0; p < P; p++)
#pragma unroll
        for (int s = 0; s < 2; s++) {
            const float* c = acc[p][s];
            int m = warpM * 16 + (lid >> 2);
            int n = warpN * W + p * 16 + s * 8 + (lid & 3) * 2;
            stage[m * ST + n]           = c[0];
            stage[m * ST + n + 1]       = c[1];
            stage[(m + 8) * ST + n]     = c[2];
            stage[(m + 8) * ST + n + 1] = c[3];
        }
    __syncthreads();

    if (EPI == 0) {
#pragma unroll
        for (int i = 0; i < (ROWS * NCOLS) / 2048; i++) {
            int idx = i * 512 + tid; int m = idx >> 5, c4 = idx & 31;
            *(float4*)(po0 + (size_t)(row0 + m) * 128 + c4 * 4) =
                *(const float4*)(stage + m * ST + c4 * 4);
        }
    } else if (EPI == 1) {
        // trop (cols 32-63) and real (cols 64-95)
#pragma unroll
        for (int i = 0; i < ROWS / 32; i++) {
            int idx = i * 512 + tid; int m = idx >> 4, c4 = idx & 15;
            float4 v = *(const float4*)(stage + m * ST + 32 + c4 * 4);
            if (c4 < 8) *(float4*)(po0 + (size_t)(row0 + m) * 32 + c4 * 4) = v;
            else        *(float4*)(po1 + (size_t)(row0 + m) * 32 + (c4 - 8) * 4) = v;
        }
        // boolean bits: warp-cooperative exact fp32 fixup for near-zero logits
        if (tid < ROWS) {
            const int rbase = row0 + (wid << 5);
            unsigned bits = 0;
#pragma unroll 4
            for (int j = 0; j < 32; j++) {
                float v = stage[tid * ST + j];
                unsigned need = __ballot_sync(0xffffffffu, fabsf(v) < kFixTh);
                while (need) {
                    int src = __ffs(need) - 1;
                    need &= need - 1;
                    const float* xr = aF + (size_t)(rbase + src) * 1024;
                    const float* wr = Bfix + (size_t)j * 1024;
                    float s = 0.f;
#pragma unroll 8
                    for (int k = lid; k < 1024; k += 32)
                        s = fmaf(xr[k], wr[k], s);
#pragma unroll
                    for (int o = 16; o > 0; o >>= 1)
                        s += __shfl_xor_sync(0xffffffffu, s, o);
                    if (lid == src) v = s;
                }
                bits |= (v > 0.f ? 1u : 0u) << j;
            }
            po2[row0 + tid] = bits;
        }
    } else { // EPI == 2: split-bf16 transposed store vpT[(b*128+h)][m]
        const int b = row0 >> 10;
        const int m0 = row0 & 1023;
        const int h = tid & 127, q4 = tid >> 7;
        constexpr int MH = ROWS / 4;
        __nv_bfloat16* vh = (__nv_bfloat16*)po0 + ((size_t)b * 128 + h) * 1024 + m0 + q4 * MH;
        __nv_bfloat16* vl = (__nv_bfloat16*)po1 + ((size_t)b * 128 + h) * 1024 + m0 + q4 * MH;
#pragma unroll
        for (int mm = 0; mm < MH; mm += 4) {
            int mb = q4 * MH + mm;
            float4 v = make_float4(stage[(mb + 0) * ST + h], stage[(mb + 1) * ST + h],
                                   stage[(mb + 2) * ST + h], stage[(mb + 3) * ST + h]);
            uint2 H, L; split_pack(v, H, L);
            *(uint2*)(vh + mm) = H;
            *(uint2*)(vl + mm) = L;
        }
    }
}

// ================================================================
// weight prep — 32x32 smem tile transpose, fully coalesced both ways.
// Blocks 0..191: six 1024x32 QK weights (src = bid>>5, dt = bid&31).
// Blocks 192..319: Wv 1024x128 (dt = t&31, jt = t>>5).
// ================================================================
__global__ __launch_bounds__(256) void wprep_kernel(
    const float* __restrict__ Wqb, const float* __restrict__ Wqt, const float* __restrict__ Wqr,
    const float* __restrict__ Wkb, const float* __restrict__ Wkt, const float* __restrict__ Wkr,
    const float* __restrict__ Wv)
{
    __shared__ float t[32][36];
    const int tid = threadIdx.x;
    const int bid = blockIdx.x;

    const float* W; int stride, jin, dt, jout;
    float* oF; __nv_bfloat16 *oH, *oL;
    if (bid < 192) {
        int src = bid >> 5; dt = bid & 31;
        stride = 32; jin = 0;
        if (src == 0)      { W = Wqb; jout = 0;  oF = g_wqT; oH = g_wqTh; oL = g_wqTl; }
        else if (src == 1) { W = Wqt; jout = 32; oF = g_wqT; oH = g_wqTh; oL = g_wqTl; }
        else if (src == 2) { W = Wqr; jout = 64; oF = g_wqT; oH = g_wqTh; oL = g_wqTl; }
        else if (src == 3) { W = Wkb; jout = 0;  oF = g_wkT; oH = g_wkTh; oL = g_wkTl; }
        else if (src == 4) { W = Wkt; jout = 32; oF = g_wkT; oH = g_wkTh; oL = g_wkTl; }
        else               { W = Wkr; jout = 64; oF = g_wkT; oH = g_wkTh; oL = g_wkTl; }
    } else {
        int t2 = bid - 192; dt = t2 & 31; int jt = t2 >> 5;
        stride = 128; jin = jt * 32; jout = jt * 32;
        W = Wv; oF = nullptr; oH = g_wvTh; oL = g_wvTl;
    }

    // coalesced load: row r of tile (d = dt*32+r), cols jin + c4..c4+3
    {
        int r = tid >> 3, c4 = (tid & 7) * 4;
        float4 v = *(const float4*)(W + (size_t)(dt * 32 + r) * stride + jin + c4);
        *(float4*)&t[r][c4] = v;
    }
    __syncthreads();

    // coalesced write: row j = tid>>3 of output, cols d = dt*32 + dc..dc+3
    {
        int j = tid >> 3, dc = (tid & 7) * 4;
        float4 v = make_float4(t[dc + 0][j], t[dc + 1][j], t[dc + 2][j], t[dc + 3][j]);
        size_t off = (size_t)(jout + j) * 1024 + dt * 32 + dc;
        if (oF) *(float4*)(oF + off) = v;
        uint2 H, L; split_pack(v, H, L);
        *(uint2*)(oH + off) = H;
        *(uint2*)(oL + off) = L;
    }
}

// ================================================================
// Fused monoid scores — 64n x 128m tile, 4x8 per thread (LDS/output 0.75)
// ================================================================
__global__ __launch_bounds__(256) void scores_kernel(
    const float* __restrict__ fw, const int* __restrict__ mask,
    float* __restrict__ attn)
{
    extern __shared__ char sm[];
    float (*qt)[32]   = (float(*)[32])(sm);                 //  8192 B
    float (*qr)[32]   = (float(*)[32])(sm + 8192);          //  8192 B
    float (*kts)[136] = (float(*)[136])(sm + 16384);        // 17408 B
    float (*krs)[136] = (float(*)[136])(sm + 33792);        // 17408 B
    unsigned* qb_s    = (unsigned*)(sm + 51200);            //   256 B
    unsigned* kb_s    = (unsigned*)(sm + 51456);            //   512 B

    const int tid = threadIdx.x;
    const int b  = blockIdx.z;
    const int n0 = blockIdx.y * 64;
    const int m0 = blockIdx.x * 128;
    const int qbase = b * Nc + n0;
    const int kbase = b * Mc + m0;

    // load Q codes (64 rows x 32)
#pragma unroll
    for (int l = 0; l < 2; l++) {
        int idx = tid + l * 256;
        int r = idx >> 3, c = (idx & 7) * 4;
        *(float4*)&qt[r][c] = *(const float4*)(g_qt + (size_t)(qbase + r) * MBITS + c);
        *(float4*)&qr[r][c] = *(const float4*)(g_qr + (size_t)(qbase + r) * MBITS + c);
    }
    // load K codes transposed (128 rows x 32 -> [d][m])
#pragma unroll
    for (int l = 0; l < 16; l++) {
        int idx = tid + l * 256;
        int r = idx >> 5, d = idx & 31;
        kts[d][r] = g_kt[(size_t)(kbase + r) * MBITS + d];
        krs[d][r] = g_kr[(size_t)(kbase + r) * MBITS + d];
    }
    if (tid < 64)            qb_s[tid]       = g_qb[qbase + tid];
    else if (tid < 192)      kb_s[tid - 64]  = g_kb[kbase + tid - 64];
    __syncthreads();

    const int tn0 = (tid >> 4) * 4;       // 16 n-groups x 4
    const int tm0 = (tid & 15) * 8;       // 16 m-groups x 8

    float tAcc[4][8];
    unsigned long long rA2[4][4];
#pragma unroll
    for (int i = 0; i < 4; i++) {
#pragma unroll
        for (int j = 0; j < 8; j++) tAcc[i][j] = NEG_INF;
#pragma unroll
        for (int j = 0; j < 4; j++) rA2[i][j] = 0ull;
    }

#pragma unroll
    for (int d0 = 0; d0 < 32; d0 += 4) {
        float qtl[4][4], qrl[4][4];
#pragma unroll
        for (int i = 0; i < 4; i++) {
            float4 t4 = *(float4*)&qt[tn0 + i][d0];
            float4 r4 = *(float4*)&qr[tn0 + i][d0];
            qtl[i][0] = t4.x; qtl[i][1] = t4.y; qtl[i][2] = t4.z; qtl[i][3] = t4.w;
            qrl[i][0] = r4.x; qrl[i][1] = r4.y; qrl[i][2] = r4.z; qrl[i][3] = r4.w;
        }
#pragma unroll
        for (int dd = 0; dd < 4; dd++) {
            ulonglong2 kta = *(const ulonglong2*)&kts[d0 + dd][tm0];
            ulonglong2 ktb = *(const ulonglong2*)&kts[d0 + dd][tm0 + 4];
            ulonglong2 kra = *(const ulonglong2*)&krs[d0 + dd][tm0];
            ulonglong2 krb = *(const ulonglong2*)&krs[d0 + dd][tm0 + 4];
#pragma unroll
            for (int i = 0; i < 4; i++) {
                unsigned long long qtd2 = bcast2(qtl[i][dd]);
                unsigned long long qrd2 = bcast2(qrl[i][dd]);
                float2 s0 = unpack2(add2(qtd2, kta.x));
                float2 s1 = unpack2(add2(qtd2, kta.y));
                float2 s2 = unpack2(add2(qtd2, ktb.x));
                float2 s3 = unpack2(add2(qtd2, ktb.y));
                tAcc[i][0] = fmaxf(tAcc[i][0], s0.x);
                tAcc[i][1] = fmaxf(tAcc[i][1], s0.y);
                tAcc[i][2] = fmaxf(tAcc[i][2], s1.x);
                tAcc[i][3] = fmaxf(tAcc[i][3], s1.y);
                tAcc[i][4] = fmaxf(tAcc[i][4], s2.x);
                tAcc[i][5] = fmaxf(tAcc[i][5], s2.y);
                tAcc[i][6] = fmaxf(tAcc[i][6], s3.x);
                tAcc[i][7] = fmaxf(tAcc[i][7], s3.y);
                fma2(rA2[i][0], qrd2, kra.x);
                fma2(rA2[i][1], qrd2, kra.y);
                fma2(rA2[i][2], qrd2, krb.x);
                fma2(rA2[i][3], qrd2, krb.y);
            }
        }
    }

    float f0 = fw[0], f1 = fw[1], f2 = fw[2];
    float fm = fmaxf(f0, fmaxf(f1, f2));
    float e0 = __expf(f0 - fm), e1 = __expf(f1 - fm), e2 = __expf(f2 - fm);
    float inv = 1.f / (e0 + e1 + e2);
    float w0 = e0 * inv, w1 = e1 * inv, w2 = e2 * inv;

    unsigned qbv[4], kbv[8];
#pragma unroll
    for (int i = 0; i < 4; i++) qbv[i] = qb_s[tn0 + i];
#pragma unroll
    for (int j = 0; j < 8; j++) kbv[j] = kb_s[tm0 + j];

#pragma unroll
    for (int i = 0; i < 4; i++) {
        size_t off = ((size_t)b * Nc + n0 + tn0 + i) * Mc + m0 + tm0;
#pragma unroll
        for (int h = 0; h < 2; h++) {
            float2 ra = unpack2(rA2[i][h * 2]);
            float2 rb = unpack2(rA2[i][h * 2 + 1]);
            int4 mk = *(const int4*)(mask + off + h * 4);
            float s0 = (w0 * (float)(32 - __popc(qbv[i] ^ kbv[h * 4 + 0])) + w1 * tAcc[i][h * 4 + 0] + w2 * ra.x) * kScale;
            float s1 = (w0 * (float)(32 - __popc(qbv[i] ^ kbv[h * 4 + 1])) + w1 * tAcc[i][h * 4 + 1] + w2 * ra.y) * kScale;
            float s2 = (w0 * (float)(32 - __popc(qbv[i] ^ kbv[h * 4 + 2])) + w1 * tAcc[i][h * 4 + 2] + w2 * rb.x) * kScale;
            float s3 = (w0 * (float)(32 - __popc(qbv[i] ^ kbv[h * 4 + 3])) + w1 * tAcc[i][h * 4 + 3] + w2 * rb.y) * kScale;
            float4 o;
            o.x = (mk.x == 0) ? NEG_INF : s0;
            o.y = (mk.y == 0) ? NEG_INF : s1;
            o.z = (mk.z == 0) ? NEG_INF : s2;
            o.w = (mk.w == 0) ? NEG_INF : s3;
            *(float4*)(attn + off + h * 4) = o;
        }
    }
}

// ================================================================
// Row softmax over M=1024 in place
// ================================================================
__global__ __launch_bounds__(256) void softmax_kernel(float* __restrict__ attn)
{
    __shared__ float red[8];
    const size_t row = blockIdx.x;
    float* p = attn + row * (size_t)Mc;
    const int tid = threadIdx.x;
    const int lane = tid & 31, wid = tid >> 5;

    float4 v = *(float4*)(p + tid * 4);
    float m = fmaxf(fmaxf(v.x, v.y), fmaxf(v.z, v.w));
#pragma unroll
    for (int o = 16; o > 0; o >>= 1) m = fmaxf(m, __shfl_xor_sync(0xffffffffu, m, o));
    if (lane == 0) red[wid] = m;
    __syncthreads();
    float bm = fmaxf(fmaxf(fmaxf(red[0], red[1]), fmaxf(red[2], red[3])),
                     fmaxf(fmaxf(red[4], red[5]), fmaxf(red[6], red[7])));
    __syncthreads();

    float4 e;
    e.x = __expf(v.x - bm); e.y = __expf(v.y - bm);
    e.z = __expf(v.z - bm); e.w = __expf(v.w - bm);
    float s = e.x + e.y + e.z + e.w;
#pragma unroll
    for (int o = 16; o > 0; o >>= 1) s += __shfl_xor_sync(0xffffffffu, s, o);
    if (lane == 0) red[wid] = s;
    __syncthreads();
    float ts = red[0] + red[1] + red[2] + red[3] + red[4] + red[5] + red[6] + red[7];
    float invs = 1.f / ts;
    e.x *= invs; e.y *= invs; e.z *= invs; e.w *= invs;
    *(float4*)(p + tid * 4) = e;
}

// ================================================================
extern "C" void kernel_launch(void* const* d_in, const int* in_sizes, int n_in,
                              void* d_out, int out_size)
{
    const float* Q    = (const float*)d_in[0];
    const float* K    = (const float*)d_in[1];
    const float* V    = (const float*)d_in[2];
    const float* Wqb  = (const float*)d_in[3];
    const float* Wkb  = (const float*)d_in[4];
    const float* Wqt  = (const float*)d_in[5];
    const float* Wkt  = (const float*)d_in[6];
    const float* Wqr  = (const float*)d_in[7];
    const float* Wkr  = (const float*)d_in[8];
    const float* Wv   = (const float*)d_in[9];
    const float* fw   = (const float*)d_in[10];
    const int*   mask = (const int*)d_in[11];

    float* out  = (float*)d_out;                         // [B,N,128]
    float* attn = (float*)d_out + (size_t)Bc * Nc * Hc;  // [B,N,M]

    float *qt, *qr, *kt, *kr, *wqT, *wkT;
    unsigned *qb, *kb;
    __nv_bfloat16 *wqTh, *wqTl, *wkTh, *wkTl, *wvTh, *wvTl;
    __nv_bfloat16 *vpTh, *vpTl;
    cudaGetSymbolAddress((void**)&qt, g_qt);
    cudaGetSymbolAddress((void**)&qr, g_qr);
    cudaGetSymbolAddress((void**)&qb, g_qb);
    cudaGetSymbolAddress((void**)&kt, g_kt);
    cudaGetSymbolAddress((void**)&kr, g_kr);
    cudaGetSymbolAddress((void**)&kb, g_kb);
    cudaGetSymbolAddress((void**)&wqT, g_wqT);
    cudaGetSymbolAddress((void**)&wkT, g_wkT);
    cudaGetSymbolAddress((void**)&wqTh, g_wqTh);
    cudaGetSymbolAddress((void**)&wqTl, g_wqTl);
    cudaGetSymbolAddress((void**)&wkTh, g_wkTh);
    cudaGetSymbolAddress((void**)&wkTl, g_wkTl);
    cudaGetSymbolAddress((void**)&wvTh, g_wvTh);
    cudaGetSymbolAddress((void**)&wvTl, g_wvTl);
    cudaGetSymbolAddress((void**)&vpTh, g_vpTh);
    cudaGetSymbolAddress((void**)&vpTl, g_vpTl);

    const int SMEM_PROJ = 3 * (128 * 144 * 2 + 96 * 144 * 2);   // 193536
    const int SMEM_VO   = 3 * (64 * 144 * 2 + 128 * 144 * 2);   // 165888
    const int SMEM_SC   = 52224;                                 // scores dynamic smem
    cudaFuncSetAttribute(lgemm_kernel<96, 1, 8, 1>,  cudaFuncAttributeMaxDynamicSharedMemorySize, SMEM_PROJ);
    cudaFuncSetAttribute(lgemm_kernel<128, 2, 4, 1>, cudaFuncAttributeMaxDynamicSharedMemorySize, SMEM_VO);
    cudaFuncSetAttribute(lgemm_kernel<128, 0, 4, 1>, cudaFuncAttributeMaxDynamicSharedMemorySize, SMEM_VO);
    cudaFuncSetAttribute(scores_kernel, cudaFuncAttributeMaxDynamicSharedMemorySize, SMEM_SC);

    // 0: weight prep (coalesced tile transpose)
    wprep_kernel<<<320, 256>>>(Wqb, Wqt, Wqr, Wkb, Wkt, Wkr, Wv);

    // 1: VP = V @ Wv (split transposed store)
    lgemm_kernel<128, 2, 4, 1><<<128, 512, SMEM_VO>>>(
        V, nullptr, nullptr, wvTh, wvTl, nullptr, (float*)vpTh, (float*)vpTl, nullptr,
        nullptr, nullptr, nullptr, nullptr, nullptr, nullptr, nullptr, 128, 0);

    // 2: Q + K projections
    lgemm_kernel<96, 1, 8, 1><<<128, 512, SMEM_PROJ>>>(
        Q, nullptr, nullptr, wqTh, wqTl, wqT, qt, qr, qb,
        K, wkTh, wkTl, wkT, kt, kr, kb, 64, 0);

    // 3: fused monoid scores, 64x128 tiles (ncu capture slot)
    scores_kernel<<<dim3(8, 16, 8), 256, SMEM_SC>>>(fw, mask, attn);

    // 4: softmax (in place)
    softmax_kernel<<<Bc * Nc, 256>>>(attn);

    // 5: out = attn @ VP — fp32 attn split in-kernel, batched B
    lgemm_kernel<128, 0, 4, 1><<<128, 512, SMEM_VO>>>(
        attn, nullptr, nullptr, vpTh, vpTl, nullptr, out, nullptr, nullptr,
        nullptr, nullptr, nullptr, nullptr, nullptr, nullptr, nullptr, 128, 1);
}

// round 13
// speedup vs baseline: 1.0672x; 1.0672x over previous
#include <cuda_runtime.h>
#include <cuda_bf16.h>
#include <math.h>
#include <stdint.h>

#define Bc 8
#define Nc 1024
#define Mc 1024
#define Dc 1024
#define Hc 128
#define MBITS 32
#define NEG_INF __int_as_float(0xff800000)

static constexpr float kScale = 0.17677669529663687f; // 1/sqrt(32)
static constexpr float kFixTh = 3e-4f;                // split-GEMM err ~1e-5 rms

// ---------------- scratch (no allocations allowed) ----------------
__device__ float    g_qt[Bc * Nc * MBITS];
__device__ float    g_qr[Bc * Nc * MBITS];
__device__ unsigned g_qb[Bc * Nc];
__device__ float    g_kt[Bc * Mc * MBITS];
__device__ float    g_kr[Bc * Mc * MBITS];
__device__ unsigned g_kb[Bc * Mc];
__device__ float    g_wqT[96 * 1024];   // fp32 transposed weights (fixup path)
__device__ float    g_wkT[96 * 1024];
__device__ __nv_bfloat16 g_wqTh[96 * 1024], g_wqTl[96 * 1024];
__device__ __nv_bfloat16 g_wkTh[96 * 1024], g_wkTl[96 * 1024];
__device__ __nv_bfloat16 g_wvTh[128 * 1024], g_wvTl[128 * 1024];
__device__ __nv_bfloat16 g_vpTh[Bc * 128 * 1024], g_vpTl[Bc * 128 * 1024];

// ================================================================
// helpers
// ================================================================
__device__ __forceinline__ uint32_t smem_u32(const void* p) {
    return (uint32_t)__cvta_generic_to_shared(p);
}
__device__ __forceinline__ void ldsm_x4(uint32_t* r, uint32_t addr) {
    asm volatile("ldmatrix.sync.aligned.m8n8.x4.shared.b16 {%0,%1,%2,%3}, [%4];"
        : "=r"(r[0]), "=r"(r[1]), "=r"(r[2]), "=r"(r[3]) : "r"(addr));
}
__device__ __forceinline__ void mma16816(float* c, const uint32_t* a, const uint32_t* b) {
    asm volatile("mma.sync.aligned.m16n8k16.row.col.f32.bf16.bf16.f32 "
        "{%0,%1,%2,%3}, {%4,%5,%6,%7}, {%8,%9}, {%0,%1,%2,%3};"
        : "+f"(c[0]), "+f"(c[1]), "+f"(c[2]), "+f"(c[3])
        : "r"(a[0]), "r"(a[1]), "r"(a[2]), "r"(a[3]), "r"(b[0]), "r"(b[1]));
}
#define CPA16(dst, src) \
    asm volatile("cp.async.cg.shared.global [%0], [%1], 16;" :: "r"(dst), "l"(src))
#define CP_COMMIT() asm volatile("cp.async.commit_group;" ::: "memory")
#define CP_WAIT1()  asm volatile("cp.async.wait_group 1;" ::: "memory")
#define CP_WAIT0()  asm volatile("cp.async.wait_group 0;" ::: "memory")

__device__ __forceinline__ void split_pack(float4 v, uint2& H, uint2& L) {
    __nv_bfloat16 h0 = __float2bfloat16(v.x), h1 = __float2bfloat16(v.y);
    __nv_bfloat16 h2 = __float2bfloat16(v.z), h3 = __float2bfloat16(v.w);
    __nv_bfloat16 l0 = __float2bfloat16(v.x - __bfloat162float(h0));
    __nv_bfloat16 l1 = __float2bfloat16(v.y - __bfloat162float(h1));
    __nv_bfloat16 l2 = __float2bfloat16(v.z - __bfloat162float(h2));
    __nv_bfloat16 l3 = __float2bfloat16(v.w - __bfloat162float(h3));
    H.x = ((uint32_t)__bfloat16_as_ushort(h1) << 16) | __bfloat16_as_ushort(h0);
    H.y = ((uint32_t)__bfloat16_as_ushort(h3) << 16) | __bfloat16_as_ushort(h2);
    L.x = ((uint32_t)__bfloat16_as_ushort(l1) << 16) | __bfloat16_as_ushort(l0);
    L.y = ((uint32_t)__bfloat16_as_ushort(l3) << 16) | __bfloat16_as_ushort(l2);
}

// packed f32x2 math (sm_100+ PTX)
__device__ __forceinline__ unsigned long long bcast2(float x) {
    unsigned long long r; unsigned xi = __float_as_uint(x);
    asm("mov.b64 %0, {%1, %1};" : "=l"(r) : "r"(xi));
    return r;
}
__device__ __forceinline__ unsigned long long add2(unsigned long long a, unsigned long long b) {
    unsigned long long r;
    asm("add.rn.f32x2 %0, %1, %2;" : "=l"(r) : "l"(a), "l"(b));
    return r;
}
__device__ __forceinline__ void fma2(unsigned long long& d, unsigned long long a, unsigned long long b) {
    asm("fma.rn.f32x2 %0, %1, %2, %0;" : "+l"(d) : "l"(a), "l"(b));
}
__device__ __forceinline__ float2 unpack2(unsigned long long v) {
    unsigned lo, hi;
    asm("mov.b64 {%0, %1}, %2;" : "=r"(lo), "=r"(hi) : "l"(v));
    return make_float2(__uint_as_float(lo), __uint_as_float(hi));
}

// ================================================================
// Split-bf16 HMMA GEMM (R9-proven config): 512 threads = 16 warps,
// 3-stage cp.async, K-chunk 64 (16 chunks), ONE sync/chunk.
// ================================================================
template<int NCOLS, int EPI, int MW, int ASPLIT>
__global__ __launch_bounds__(512, 1) void lgemm_kernel(
    const float* __restrict__ aF0,
    const __nv_bfloat16* __restrict__ aH0, const __nv_bfloat16* __restrict__ aL0,
    const __nv_bfloat16* __restrict__ bH0, const __nv_bfloat16* __restrict__ bL0,
    const float* __restrict__ Bfix0,
    float* __restrict__ p0, float* __restrict__ p1, unsigned* __restrict__ p2,
    const float* __restrict__ aF1,
    const __nv_bfloat16* __restrict__ bH1, const __nv_bfloat16* __restrict__ bL1,
    const float* __restrict__ Bfix1,
    float* __restrict__ q0, float* __restrict__ q1, unsigned* __restrict__ q2,
    int tilesPerSide, int batchB)
{
    extern __shared__ char smem[];
    constexpr int NW   = 16 / MW;
    constexpr int ROWS = MW * 16;
    constexpr int W    = NCOLS / NW;
    constexpr int P    = W / 16;
    constexpr int SKP  = 72;
    constexpr int AB   = ROWS * 144;
    constexpr int BB   = NCOLS * 144;
    constexpr int STG  = 2 * AB + 2 * BB;
    constexpr int ALD  = (ROWS * 16) / 512;
    constexpr int ACP  = (ROWS * 8 + 511) / 512;
    constexpr int BCP  = (NCOLS * 8 + 511) / 512;
    constexpr int ST   = NCOLS + 4;

    const int tid = threadIdx.x;
    const int wid = tid >> 5, lid = tid & 31;
    const int warpM = wid % MW, warpN = wid / MW;

    const float* aF = aF0;
    const __nv_bfloat16 *aH = aH0, *aL = aL0, *bH = bH0, *bL = bL0;
    const float* Bfix = Bfix0;
    float* po0 = p0; float* po1 = p1; unsigned* po2 = p2;
    int row0 = blockIdx.x * ROWS;
    if (EPI == 1 && blockIdx.x >= tilesPerSide) {
        row0 = (blockIdx.x - tilesPerSide) * ROWS;
        aF = aF1; bH = bH1; bL = bL1; Bfix = Bfix1;
        po0 = q0; po1 = q1; po2 = q2;
    }
    size_t bBase = 0;
    if (batchB) bBase = (size_t)(row0 >> 10) * NCOLS * 1024;

    const uint32_t sb = smem_u32(smem);

    auto issueB = [&](int kc, int st) {
        const uint32_t base = sb + st * STG + 2 * AB;
        const int kof = kc * 64;
#pragma unroll
        for (int i = 0; i < BCP; i++) {
            int idx = i * 512 + tid;
            if ((NCOLS * 8) % 512 == 0 || idx < NCOLS * 8) {
                int r = idx >> 3, c = idx & 7;
                size_t so = bBase + (size_t)r * 1024 + kof + c * 8;
                uint32_t dof = base + r * 144 + c * 16;
                CPA16(dof, bH + so);
                CPA16(dof + BB, bL + so);
            }
        }
    };
    auto issueA = [&](int kc, int st) {
        const uint32_t base = sb + st * STG;
        const int kof = kc * 64;
#pragma unroll
        for (int i = 0; i < ACP; i++) {
            int idx = i * 512 + tid;
            if ((ROWS * 8) % 512 == 0 || idx < ROWS * 8) {
                int r = idx >> 3, c = idx & 7;
                size_t so = (size_t)(row0 + r) * 1024 + kof + c * 8;
                uint32_t dof = base + r * 144 + c * 16;
                CPA16(dof, aH + so);
                CPA16(dof + AB, aL + so);
            }
        }
    };
    float4 av[ASPLIT ? ALD : 1];
    auto loadA = [&](int kc) {
#pragma unroll
        for (int i = 0; i < ALD; i++) {
            int idx = i * 512 + tid; int r = idx >> 4, c4 = idx & 15;
            av[i] = *(const float4*)(aF + (size_t)(row0 + r) * 1024 + kc * 64 + c4 * 4);
        }
    };
    auto storeA = [&](int st) {
        char* base = smem + st * STG;
#pragma unroll
        for (int i = 0; i < ALD; i++) {
            int idx = i * 512 + tid; int r = idx >> 4, c4 = idx & 15;
            int off = r * 144 + c4 * 8;
            uint2 H, L; split_pack(av[i], H, L);
            *(uint2*)(base + off) = H;
            *(uint2*)(base + AB + off) = L;
        }
    };

    float acc[P][2][4];
#pragma unroll
    for (int p = 0; p < P; p++)
#pragma unroll
        for (int s = 0; s < 2; s++)
#pragma unroll
            for (int e = 0; e < 4; e++) acc[p][s][e] = 0.f;

    const int aRowB = warpM * 16 + (lid & 15);
    const int aKoff = (lid >> 4) << 3;
    const int bRowB = warpN * W + (lid & 7) + ((lid & 16) >> 1);
    const int bKoff = (lid & 8);

    if (ASPLIT) loadA(0);
    else        issueA(0, 0);
    issueB(0, 0); CP_COMMIT();
    if (!ASPLIT) issueA(1, 1);
    issueB(1, 1); CP_COMMIT();

    int st = 0;
    for (int kc = 0; kc < 16; kc++) {
        if (ASPLIT) {
            storeA(st);
            if (kc < 15) loadA(kc + 1);
        }
        if (kc < 15) CP_WAIT1(); else CP_WAIT0();
        __syncthreads();

        if (kc + 2 < 16) {
            int st2 = st + 2; if (st2 >= 3) st2 -= 3;
            if (!ASPLIT) issueA(kc + 2, st2);
            issueB(kc + 2, st2);
            CP_COMMIT();
        }

        const uint32_t base = sb + st * STG;
#pragma unroll
        for (int ks = 0; ks < 4; ks++) {
            uint32_t ah[4], al[4];
            uint32_t aAddr = base + (uint32_t)(aRowB * SKP + ks * 16 + aKoff) * 2;
            ldsm_x4(ah, aAddr);
            ldsm_x4(al, aAddr + AB);
#pragma unroll
            for (int p = 0; p < P; p++) {
                uint32_t bh[4], bl[4];
                uint32_t bAddr = base + 2 * AB +
                    (uint32_t)((bRowB + p * 16) * SKP + ks * 16 + bKoff) * 2;
                ldsm_x4(bh, bAddr);
                ldsm_x4(bl, bAddr + BB);
                mma16816(acc[p][0], ah, &bh[0]);
                mma16816(acc[p][1], ah, &bh[2]);
                mma16816(acc[p][0], ah, &bl[0]);
                mma16816(acc[p][1], ah, &bl[2]);
                mma16816(acc[p][0], al, &bh[0]);
                mma16816(acc[p][1], al, &bh[2]);
            }
        }
        if (++st == 3) st = 0;
    }
    __syncthreads();

    // ---- stage C to smem ----
    float* stage = (float*)smem;
#pragma unroll
    for (int p = 0; p < P; p++)
#pragma unroll
        for (int s = 0; s < 2; s++) {
            const float* c = acc[p][s];
            int m = warpM * 16 + (lid >> 2);
            int n = warpN * W + p * 16 + s * 8 + (lid & 3) * 2;
            stage[m * ST + n]           = c[0];
            stage[m * ST + n + 1]       = c[1];
            stage[(m + 8) * ST + n]     = c[2];
            stage[(m + 8) * ST + n + 1] = c[3];
        }
    __syncthreads();

    if (EPI == 0) {
#pragma unroll
        for (int i = 0; i < (ROWS * NCOLS) / 2048; i++) {
            int idx = i * 512 + tid; int m = idx >> 5, c4 = idx & 31;
            *(float4*)(po0 + (size_t)(row0 + m) * 128 + c4 * 4) =
                *(const float4*)(stage + m * ST + c4 * 4);
        }
    } else if (EPI == 1) {
        // trop (cols 32-63) and real (cols 64-95)
#pragma unroll
        for (int i = 0; i < ROWS / 32; i++) {
            int idx = i * 512 + tid; int m = idx >> 4, c4 = idx & 15;
            float4 v = *(const float4*)(stage + m * ST + 32 + c4 * 4);
            if (c4 < 8) *(float4*)(po0 + (size_t)(row0 + m) * 32 + c4 * 4) = v;
            else        *(float4*)(po1 + (size_t)(row0 + m) * 32 + (c4 - 8) * 4) = v;
        }
        // boolean bits: warp-cooperative exact fp32 fixup for near-zero logits
        if (tid < ROWS) {
            const int rbase = row0 + (wid << 5);
            unsigned bits = 0;
#pragma unroll 4
            for (int j = 0; j < 32; j++) {
                float v = stage[tid * ST + j];
                unsigned need = __ballot_sync(0xffffffffu, fabsf(v) < kFixTh);
                while (need) {
                    int src = __ffs(need) - 1;
                    need &= need - 1;
                    const float* xr = aF + (size_t)(rbase + src) * 1024;
                    const float* wr = Bfix + (size_t)j * 1024;
                    float s = 0.f;
#pragma unroll 8
                    for (int k = lid; k < 1024; k += 32)
                        s = fmaf(xr[k], wr[k], s);
#pragma unroll
                    for (int o = 16; o > 0; o >>= 1)
                        s += __shfl_xor_sync(0xffffffffu, s, o);
                    if (lid == src) v = s;
                }
                bits |= (v > 0.f ? 1u : 0u) << j;
            }
            po2[row0 + tid] = bits;
        }
    } else { // EPI == 2: split-bf16 transposed store vpT[(b*128+h)][m]
        const int b = row0 >> 10;
        const int m0 = row0 & 1023;
        const int h = tid & 127, q4 = tid >> 7;
        constexpr int MH = ROWS / 4;
        __nv_bfloat16* vh = (__nv_bfloat16*)po0 + ((size_t)b * 128 + h) * 1024 + m0 + q4 * MH;
        __nv_bfloat16* vl = (__nv_bfloat16*)po1 + ((size_t)b * 128 + h) * 1024 + m0 + q4 * MH;
#pragma unroll
        for (int mm = 0; mm < MH; mm += 4) {
            int mb = q4 * MH + mm;
            float4 v = make_float4(stage[(mb + 0) * ST + h], stage[(mb + 1) * ST + h],
                                   stage[(mb + 2) * ST + h], stage[(mb + 3) * ST + h]);
            uint2 H, L; split_pack(v, H, L);
            *(uint2*)(vh + mm) = H;
            *(uint2*)(vl + mm) = L;
        }
    }
}

// ================================================================
// weight prep — 32x32 smem tile transpose, fully coalesced both ways
// ================================================================
__global__ __launch_bounds__(256) void wprep_kernel(
    const float* __restrict__ Wqb, const float* __restrict__ Wqt, const float* __restrict__ Wqr,
    const float* __restrict__ Wkb, const float* __restrict__ Wkt, const float* __restrict__ Wkr,
    const float* __restrict__ Wv)
{
    __shared__ float t[32][36];
    const int tid = threadIdx.x;
    const int bid = blockIdx.x;

    const float* W; int stride, jin, dt, jout;
    float* oF; __nv_bfloat16 *oH, *oL;
    if (bid < 192) {
        int src = bid >> 5; dt = bid & 31;
        stride = 32; jin = 0;
        if (src == 0)      { W = Wqb; jout = 0;  oF = g_wqT; oH = g_wqTh; oL = g_wqTl; }
        else if (src == 1) { W = Wqt; jout = 32; oF = g_wqT; oH = g_wqTh; oL = g_wqTl; }
        else if (src == 2) { W = Wqr; jout = 64; oF = g_wqT; oH = g_wqTh; oL = g_wqTl; }
        else if (src == 3) { W = Wkb; jout = 0;  oF = g_wkT; oH = g_wkTh; oL = g_wkTl; }
        else if (src == 4) { W = Wkt; jout = 32; oF = g_wkT; oH = g_wkTh; oL = g_wkTl; }
        else               { W = Wkr; jout = 64; oF = g_wkT; oH = g_wkTh; oL = g_wkTl; }
    } else {
        int t2 = bid - 192; dt = t2 & 31; int jt = t2 >> 5;
        stride = 128; jin = jt * 32; jout = jt * 32;
        W = Wv; oF = nullptr; oH = g_wvTh; oL = g_wvTl;
    }

    {
        int r = tid >> 3, c4 = (tid & 7) * 4;
        float4 v = *(const float4*)(W + (size_t)(dt * 32 + r) * stride + jin + c4);
        *(float4*)&t[r][c4] = v;
    }
    __syncthreads();
    {
        int j = tid >> 3, dc = (tid & 7) * 4;
        float4 v = make_float4(t[dc + 0][j], t[dc + 1][j], t[dc + 2][j], t[dc + 3][j]);
        size_t off = (size_t)(jout + j) * 1024 + dt * 32 + dc;
        if (oF) *(float4*)(oF + off) = v;
        uint2 H, L; split_pack(v, H, L);
        *(uint2*)(oH + off) = H;
        *(uint2*)(oL + off) = L;
    }
}

// ================================================================
// Fused monoid scores — R11-proven 64x64 tile, 4x4/thread
// ================================================================
__global__ __launch_bounds__(256) void scores_kernel(
    const float* __restrict__ fw, const int* __restrict__ mask,
    float* __restrict__ attn)
{
    __shared__ float qt[64][32];
    __shared__ float qr[64][32];
    __shared__ float kts[32][68];
    __shared__ float krs[32][68];
    __shared__ unsigned qb_s[64];
    __shared__ unsigned kb_s[64];

    const int tid = threadIdx.x;
    const int b  = blockIdx.z;
    const int n0 = blockIdx.y * 64;
    const int m0 = blockIdx.x * 64;
    const int qbase = b * Nc + n0;
    const int kbase = b * Mc + m0;

#pragma unroll
    for (int l = 0; l < 2; l++) {
        int idx = tid + l * 256;
        int r = idx >> 3, c = (idx & 7) * 4;
        *(float4*)&qt[r][c] = *(const float4*)(g_qt + (size_t)(qbase + r) * MBITS + c);
        *(float4*)&qr[r][c] = *(const float4*)(g_qr + (size_t)(qbase + r) * MBITS + c);
    }
#pragma unroll
    for (int l = 0; l < 8; l++) {
        int idx = tid + l * 256;
        int r = idx >> 5, d = idx & 31;
        kts[d][r] = g_kt[(size_t)(kbase + r) * MBITS + d];
        krs[d][r] = g_kr[(size_t)(kbase + r) * MBITS + d];
    }
    if (tid < 64)            qb_s[tid]       = g_qb[qbase + tid];
    else if (tid < 128)      kb_s[tid - 64]  = g_kb[kbase + tid - 64];
    __syncthreads();

    const int tn0 = (tid >> 4) * 4;
    const int tm0 = (tid & 15) * 4;

    float tAcc[4][4];
    unsigned long long rA2[4][2];
#pragma unroll
    for (int i = 0; i < 4; i++) {
#pragma unroll
        for (int j = 0; j < 4; j++) tAcc[i][j] = NEG_INF;
        rA2[i][0] = 0ull; rA2[i][1] = 0ull;
    }

#pragma unroll
    for (int d0 = 0; d0 < 32; d0 += 4) {
        float qtl[4][4], qrl[4][4];
#pragma unroll
        for (int i = 0; i < 4; i++) {
            float4 t = *(float4*)&qt[tn0 + i][d0];
            float4 r = *(float4*)&qr[tn0 + i][d0];
            qtl[i][0] = t.x; qtl[i][1] = t.y; qtl[i][2] = t.z; qtl[i][3] = t.w;
            qrl[i][0] = r.x; qrl[i][1] = r.y; qrl[i][2] = r.z; qrl[i][3] = r.w;
        }
#pragma unroll
        for (int dd = 0; dd < 4; dd++) {
            ulonglong2 kt2 = *(const ulonglong2*)&kts[d0 + dd][tm0];
            ulonglong2 kr2 = *(const ulonglong2*)&krs[d0 + dd][tm0];
#pragma unroll
            for (int i = 0; i < 4; i++) {
                unsigned long long qtd2 = bcast2(qtl[i][dd]);
                unsigned long long qrd2 = bcast2(qrl[i][dd]);
                float2 s0 = unpack2(add2(qtd2, kt2.x));
                float2 s1 = unpack2(add2(qtd2, kt2.y));
                tAcc[i][0] = fmaxf(tAcc[i][0], s0.x);
                tAcc[i][1] = fmaxf(tAcc[i][1], s0.y);
                tAcc[i][2] = fmaxf(tAcc[i][2], s1.x);
                tAcc[i][3] = fmaxf(tAcc[i][3], s1.y);
                fma2(rA2[i][0], qrd2, kr2.x);
                fma2(rA2[i][1], qrd2, kr2.y);
            }
        }
    }

    float f0 = fw[0], f1 = fw[1], f2 = fw[2];
    float fm = fmaxf(f0, fmaxf(f1, f2));
    float e0 = __expf(f0 - fm), e1 = __expf(f1 - fm), e2 = __expf(f2 - fm);
    float inv = 1.f / (e0 + e1 + e2);
    float w0 = e0 * inv, w1 = e1 * inv, w2 = e2 * inv;

    unsigned qbv[4], kbv[4];
#pragma unroll
    for (int i = 0; i < 4; i++) qbv[i] = qb_s[tn0 + i];
#pragma unroll
    for (int j = 0; j < 4; j++) kbv[j] = kb_s[tm0 + j];

#pragma unroll
    for (int i = 0; i < 4; i++) {
        float2 r01 = unpack2(rA2[i][0]);
        float2 r23 = unpack2(rA2[i][1]);
        size_t off = ((size_t)b * Nc + n0 + tn0 + i) * Mc + m0 + tm0;
        int4 mk = *(const int4*)(mask + off);
        float s0 = (w0 * (float)(32 - __popc(qbv[i] ^ kbv[0])) + w1 * tAcc[i][0] + w2 * r01.x) * kScale;
        float s1 = (w0 * (float)(32 - __popc(qbv[i] ^ kbv[1])) + w1 * tAcc[i][1] + w2 * r01.y) * kScale;
        float s2 = (w0 * (float)(32 - __popc(qbv[i] ^ kbv[2])) + w1 * tAcc[i][2] + w2 * r23.x) * kScale;
        float s3 = (w0 * (float)(32 - __popc(qbv[i] ^ kbv[3])) + w1 * tAcc[i][3] + w2 * r23.y) * kScale;
        float4 o;
        o.x = (mk.x == 0) ? NEG_INF : s0;
        o.y = (mk.y == 0) ? NEG_INF : s1;
        o.z = (mk.z == 0) ? NEG_INF : s2;
        o.w = (mk.w == 0) ? NEG_INF : s3;
        *(float4*)(attn + off) = o;
    }
}

// ================================================================
// Row softmax over M=1024 in place
// ================================================================
__global__ __launch_bounds__(256) void softmax_kernel(float* __restrict__ attn)
{
    __shared__ float red[8];
    const size_t row = blockIdx.x;
    float* p = attn + row * (size_t)Mc;
    const int tid = threadIdx.x;
    const int lane = tid & 31, wid = tid >> 5;

    float4 v = *(float4*)(p + tid * 4);
    float m = fmaxf(fmaxf(v.x, v.y), fmaxf(v.z, v.w));
#pragma unroll
    for (int o = 16; o > 0; o >>= 1) m = fmaxf(m, __shfl_xor_sync(0xffffffffu, m, o));
    if (lane == 0) red[wid] = m;
    __syncthreads();
    float bm = fmaxf(fmaxf(fmaxf(red[0], red[1]), fmaxf(red[2], red[3])),
                     fmaxf(fmaxf(red[4], red[5]), fmaxf(red[6], red[7])));
    __syncthreads();

    float4 e;
    e.x = __expf(v.x - bm); e.y = __expf(v.y - bm);
    e.z = __expf(v.z - bm); e.w = __expf(v.w - bm);
    float s = e.x + e.y + e.z + e.w;
#pragma unroll
    for (int o = 16; o > 0; o >>= 1) s += __shfl_xor_sync(0xffffffffu, s, o);
    if (lane == 0) red[wid] = s;
    __syncthreads();
    float ts = red[0] + red[1] + red[2] + red[3] + red[4] + red[5] + red[6] + red[7];
    float invs = 1.f / ts;
    e.x *= invs; e.y *= invs; e.z *= invs; e.w *= invs;
    *(float4*)(p + tid * 4) = e;
}

// ================================================================
extern "C" void kernel_launch(void* const* d_in, const int* in_sizes, int n_in,
                              void* d_out, int out_size)
{
    const float* Q    = (const float*)d_in[0];
    const float* K    = (const float*)d_in[1];
    const float* V    = (const float*)d_in[2];
    const float* Wqb  = (const float*)d_in[3];
    const float* Wkb  = (const float*)d_in[4];
    const float* Wqt  = (const float*)d_in[5];
    const float* Wkt  = (const float*)d_in[6];
    const float* Wqr  = (const float*)d_in[7];
    const float* Wkr  = (const float*)d_in[8];
    const float* Wv   = (const float*)d_in[9];
    const float* fw   = (const float*)d_in[10];
    const int*   mask = (const int*)d_in[11];

    float* out  = (float*)d_out;                         // [B,N,128]
    float* attn = (float*)d_out + (size_t)Bc * Nc * Hc;  // [B,N,M]

    float *qt, *qr, *kt, *kr, *wqT, *wkT;
    unsigned *qb, *kb;
    __nv_bfloat16 *wqTh, *wqTl, *wkTh, *wkTl, *wvTh, *wvTl;
    __nv_bfloat16 *vpTh, *vpTl;
    cudaGetSymbolAddress((void**)&qt, g_qt);
    cudaGetSymbolAddress((void**)&qr, g_qr);
    cudaGetSymbolAddress((void**)&qb, g_qb);
    cudaGetSymbolAddress((void**)&kt, g_kt);
    cudaGetSymbolAddress((void**)&kr, g_kr);
    cudaGetSymbolAddress((void**)&kb, g_kb);
    cudaGetSymbolAddress((void**)&wqT, g_wqT);
    cudaGetSymbolAddress((void**)&wkT, g_wkT);
    cudaGetSymbolAddress((void**)&wqTh, g_wqTh);
    cudaGetSymbolAddress((void**)&wqTl, g_wqTl);
    cudaGetSymbolAddress((void**)&wkTh, g_wkTh);
    cudaGetSymbolAddress((void**)&wkTl, g_wkTl);
    cudaGetSymbolAddress((void**)&wvTh, g_wvTh);
    cudaGetSymbolAddress((void**)&wvTl, g_wvTl);
    cudaGetSymbolAddress((void**)&vpTh, g_vpTh);
    cudaGetSymbolAddress((void**)&vpTl, g_vpTl);

    const int SMEM_PROJ = 3 * (128 * 144 * 2 + 96 * 144 * 2);   // 193536
    const int SMEM_VO   = 3 * (64 * 144 * 2 + 128 * 144 * 2);   // 165888
    cudaFuncSetAttribute(lgemm_kernel<96, 1, 8, 1>,  cudaFuncAttributeMaxDynamicSharedMemorySize, SMEM_PROJ);
    cudaFuncSetAttribute(lgemm_kernel<128, 2, 4, 1>, cudaFuncAttributeMaxDynamicSharedMemorySize, SMEM_VO);
    cudaFuncSetAttribute(lgemm_kernel<128, 0, 4, 1>, cudaFuncAttributeMaxDynamicSharedMemorySize, SMEM_VO);

    // side stream for VP overlap (created once, outside capture; the
    // correctness call precedes graph capture)
    static cudaStream_t s2 = nullptr;
    static cudaEvent_t evF = nullptr, evJ = nullptr;
    if (s2 == nullptr) {
        cudaStreamCreateWithFlags(&s2, cudaStreamNonBlocking);
        cudaEventCreateWithFlags(&evF, cudaEventDisableTiming);
        cudaEventCreateWithFlags(&evJ, cudaEventDisableTiming);
    }

    // 0: weight prep (coalesced tile transpose)
    wprep_kernel<<<320, 256>>>(Wqb, Wqt, Wqr, Wkb, Wkt, Wkr, Wv);

    // fork: VP on side stream (depends only on wprep); overlaps proj+scores
    cudaEventRecord(evF, 0);
    cudaStreamWaitEvent(s2, evF, 0);
    lgemm_kernel<128, 2, 4, 1><<<128, 512, SMEM_VO, s2>>>(
        V, nullptr, nullptr, wvTh, wvTl, nullptr, (float*)vpTh, (float*)vpTl, nullptr,
        nullptr, nullptr, nullptr, nullptr, nullptr, nullptr, nullptr, 128, 0);

    // main stream: Q + K projections
    lgemm_kernel<96, 1, 8, 1><<<128, 512, SMEM_PROJ>>>(
        Q, nullptr, nullptr, wqTh, wqTl, wqT, qt, qr, qb,
        K, wkTh, wkTl, wkT, kt, kr, kb, 64, 0);

    // fused monoid scores (overlaps VP tail)
    scores_kernel<<<dim3(16, 16, 8), 256>>>(fw, mask, attn);

    // softmax (in place)
    softmax_kernel<<<Bc * Nc, 256>>>(attn);

    // join: out needs VP + softmax
    cudaEventRecord(evJ, s2);
    cudaStreamWaitEvent(0, evJ, 0);
    lgemm_kernel<128, 0, 4, 1><<<128, 512, SMEM_VO>>>(
        attn, nullptr, nullptr, vpTh, vpTl, nullptr, out, nullptr, nullptr,
        nullptr, nullptr, nullptr, nullptr, nullptr, nullptr, nullptr, 128, 1);
}

// round 14
// speedup vs baseline: 1.1109x; 1.0410x over previous
#include <cuda_runtime.h>
#include <cuda_bf16.h>
#include <math.h>
#include <stdint.h>

#define Bc 8
#define Nc 1024
#define Mc 1024
#define Dc 1024
#define Hc 128
#define MBITS 32
#define NEG_INF __int_as_float(0xff800000)

static constexpr float kScale = 0.17677669529663687f; // 1/sqrt(32)
static constexpr float kFixTh = 3e-4f;                // split-GEMM err ~1e-5 rms

// ---------------- scratch (no allocations allowed) ----------------
__device__ float    g_qt[Bc * Nc * MBITS];
__device__ float    g_qr[Bc * Nc * MBITS];
__device__ unsigned g_qb[Bc * Nc];
__device__ float    g_kt[Bc * Mc * MBITS];
__device__ float    g_kr[Bc * Mc * MBITS];
__device__ unsigned g_kb[Bc * Mc];
__device__ float    g_wqT[96 * 1024];   // fp32 transposed weights (fixup path)
__device__ float    g_wkT[96 * 1024];
__device__ __nv_bfloat16 g_wqTh[96 * 1024], g_wqTl[96 * 1024];
__device__ __nv_bfloat16 g_wkTh[96 * 1024], g_wkTl[96 * 1024];
__device__ __nv_bfloat16 g_wvTh[128 * 1024], g_wvTl[128 * 1024];
__device__ __nv_bfloat16 g_vpTh[Bc * 128 * 1024], g_vpTl[Bc * 128 * 1024];

// ================================================================
// helpers
// ================================================================
__device__ __forceinline__ uint32_t smem_u32(const void* p) {
    return (uint32_t)__cvta_generic_to_shared(p);
}
__device__ __forceinline__ void ldsm_x4(uint32_t* r, uint32_t addr) {
    asm volatile("ldmatrix.sync.aligned.m8n8.x4.shared.b16 {%0,%1,%2,%3}, [%4];"
        : "=r"(r[0]), "=r"(r[1]), "=r"(r[2]), "=r"(r[3]) : "r"(addr));
}
__device__ __forceinline__ void mma16816(float* c, const uint32_t* a, const uint32_t* b) {
    asm volatile("mma.sync.aligned.m16n8k16.row.col.f32.bf16.bf16.f32 "
        "{%0,%1,%2,%3}, {%4,%5,%6,%7}, {%8,%9}, {%0,%1,%2,%3};"
        : "+f"(c[0]), "+f"(c[1]), "+f"(c[2]), "+f"(c[3])
        : "r"(a[0]), "r"(a[1]), "r"(a[2]), "r"(a[3]), "r"(b[0]), "r"(b[1]));
}
#define CPA16(dst, src) \
    asm volatile("cp.async.cg.shared.global [%0], [%1], 16;" :: "r"(dst), "l"(src))
#define CP_COMMIT() asm volatile("cp.async.commit_group;" ::: "memory")
#define CP_WAIT1()  asm volatile("cp.async.wait_group 1;" ::: "memory")
#define CP_WAIT0()  asm volatile("cp.async.wait_group 0;" ::: "memory")

__device__ __forceinline__ void split_pack(float4 v, uint2& H, uint2& L) {
    __nv_bfloat16 h0 = __float2bfloat16(v.x), h1 = __float2bfloat16(v.y);
    __nv_bfloat16 h2 = __float2bfloat16(v.z), h3 = __float2bfloat16(v.w);
    __nv_bfloat16 l0 = __float2bfloat16(v.x - __bfloat162float(h0));
    __nv_bfloat16 l1 = __float2bfloat16(v.y - __bfloat162float(h1));
    __nv_bfloat16 l2 = __float2bfloat16(v.z - __bfloat162float(h2));
    __nv_bfloat16 l3 = __float2bfloat16(v.w - __bfloat162float(h3));
    H.x = ((uint32_t)__bfloat16_as_ushort(h1) << 16) | __bfloat16_as_ushort(h0);
    H.y = ((uint32_t)__bfloat16_as_ushort(h3) << 16) | __bfloat16_as_ushort(h2);
    L.x = ((uint32_t)__bfloat16_as_ushort(l1) << 16) | __bfloat16_as_ushort(l0);
    L.y = ((uint32_t)__bfloat16_as_ushort(l3) << 16) | __bfloat16_as_ushort(l2);
}

// packed f32x2 math (sm_100+ PTX)
__device__ __forceinline__ unsigned long long bcast2(float x) {
    unsigned long long r; unsigned xi = __float_as_uint(x);
    asm("mov.b64 %0, {%1, %1};" : "=l"(r) : "r"(xi));
    return r;
}
__device__ __forceinline__ unsigned long long add2(unsigned long long a, unsigned long long b) {
    unsigned long long r;
    asm("add.rn.f32x2 %0, %1, %2;" : "=l"(r) : "l"(a), "l"(b));
    return r;
}
__device__ __forceinline__ void fma2(unsigned long long& d, unsigned long long a, unsigned long long b) {
    asm("fma.rn.f32x2 %0, %1, %2, %0;" : "+l"(d) : "l"(a), "l"(b));
}
__device__ __forceinline__ float2 unpack2(unsigned long long v) {
    unsigned lo, hi;
    asm("mov.b64 {%0, %1}, %2;" : "=r"(lo), "=r"(hi) : "l"(v));
    return make_float2(__uint_as_float(lo), __uint_as_float(hi));
}

// ================================================================
// Split-bf16 HMMA GEMM (R9-proven config): 512 threads = 16 warps,
// 3-stage cp.async, K-chunk 64 (16 chunks), ONE sync/chunk.
// ================================================================
template<int NCOLS, int EPI, int MW, int ASPLIT>
__global__ __launch_bounds__(512, 1) void lgemm_kernel(
    const float* __restrict__ aF0,
    const __nv_bfloat16* __restrict__ aH0, const __nv_bfloat16* __restrict__ aL0,
    const __nv_bfloat16* __restrict__ bH0, const __nv_bfloat16* __restrict__ bL0,
    const float* __restrict__ Bfix0,
    float* __restrict__ p0, float* __restrict__ p1, unsigned* __restrict__ p2,
    const float* __restrict__ aF1,
    const __nv_bfloat16* __restrict__ bH1, const __nv_bfloat16* __restrict__ bL1,
    const float* __restrict__ Bfix1,
    float* __restrict__ q0, float* __restrict__ q1, unsigned* __restrict__ q2,
    int tilesPerSide, int batchB)
{
    extern __shared__ char smem[];
    constexpr int NW   = 16 / MW;
    constexpr int ROWS = MW * 16;
    constexpr int W    = NCOLS / NW;
    constexpr int P    = W / 16;
    constexpr int SKP  = 72;
    constexpr int AB   = ROWS * 144;
    constexpr int BB   = NCOLS * 144;
    constexpr int STG  = 2 * AB + 2 * BB;
    constexpr int ALD  = (ROWS * 16) / 512;
    constexpr int ACP  = (ROWS * 8 + 511) / 512;
    constexpr int BCP  = (NCOLS * 8 + 511) / 512;
    constexpr int ST   = NCOLS + 4;

    const int tid = threadIdx.x;
    const int wid = tid >> 5, lid = tid & 31;
    const int warpM = wid % MW, warpN = wid / MW;

    const float* aF = aF0;
    const __nv_bfloat16 *aH = aH0, *aL = aL0, *bH = bH0, *bL = bL0;
    const float* Bfix = Bfix0;
    float* po0 = p0; float* po1 = p1; unsigned* po2 = p2;
    int row0 = blockIdx.x * ROWS;
    if (EPI == 1 && blockIdx.x >= tilesPerSide) {
        row0 = (blockIdx.x - tilesPerSide) * ROWS;
        aF = aF1; bH = bH1; bL = bL1; Bfix = Bfix1;
        po0 = q0; po1 = q1; po2 = q2;
    }
    size_t bBase = 0;
    if (batchB) bBase = (size_t)(row0 >> 10) * NCOLS * 1024;

    const uint32_t sb = smem_u32(smem);

    auto issueB = [&](int kc, int st) {
        const uint32_t base = sb + st * STG + 2 * AB;
        const int kof = kc * 64;
#pragma unroll
        for (int i = 0; i < BCP; i++) {
            int idx = i * 512 + tid;
            if ((NCOLS * 8) % 512 == 0 || idx < NCOLS * 8) {
                int r = idx >> 3, c = idx & 7;
                size_t so = bBase + (size_t)r * 1024 + kof + c * 8;
                uint32_t dof = base + r * 144 + c * 16;
                CPA16(dof, bH + so);
                CPA16(dof + BB, bL + so);
            }
        }
    };
    auto issueA = [&](int kc, int st) {
        const uint32_t base = sb + st * STG;
        const int kof = kc * 64;
#pragma unroll
        for (int i = 0; i < ACP; i++) {
            int idx = i * 512 + tid;
            if ((ROWS * 8) % 512 == 0 || idx < ROWS * 8) {
                int r = idx >> 3, c = idx & 7;
                size_t so = (size_t)(row0 + r) * 1024 + kof + c * 8;
                uint32_t dof = base + r * 144 + c * 16;
                CPA16(dof, aH + so);
                CPA16(dof + AB, aL + so);
            }
        }
    };
    float4 av[ASPLIT ? ALD : 1];
    auto loadA = [&](int kc) {
#pragma unroll
        for (int i = 0; i < ALD; i++) {
            int idx = i * 512 + tid; int r = idx >> 4, c4 = idx & 15;
            av[i] = *(const float4*)(aF + (size_t)(row0 + r) * 1024 + kc * 64 + c4 * 4);
        }
    };
    auto storeA = [&](int st) {
        char* base = smem + st * STG;
#pragma unroll
        for (int i = 0; i < ALD; i++) {
            int idx = i * 512 + tid; int r = idx >> 4, c4 = idx & 15;
            int off = r * 144 + c4 * 8;
            uint2 H, L; split_pack(av[i], H, L);
            *(uint2*)(base + off) = H;
            *(uint2*)(base + AB + off) = L;
        }
    };

    float acc[P][2][4];
#pragma unroll
    for (int p = 0; p < P; p++)
#pragma unroll
        for (int s = 0; s < 2; s++)
#pragma unroll
            for (int e = 0; e < 4; e++) acc[p][s][e] = 0.f;

    const int aRowB = warpM * 16 + (lid & 15);
    const int aKoff = (lid >> 4) << 3;
    const int bRowB = warpN * W + (lid & 7) + ((lid & 16) >> 1);
    const int bKoff = (lid & 8);

    if (ASPLIT) loadA(0);
    else        issueA(0, 0);
    issueB(0, 0); CP_COMMIT();
    if (!ASPLIT) issueA(1, 1);
    issueB(1, 1); CP_COMMIT();

    int st = 0;
    for (int kc = 0; kc < 16; kc++) {
        if (ASPLIT) {
            storeA(st);
            if (kc < 15) loadA(kc + 1);
        }
        if (kc < 15) CP_WAIT1(); else CP_WAIT0();
        __syncthreads();

        if (kc + 2 < 16) {
            int st2 = st + 2; if (st2 >= 3) st2 -= 3;
            if (!ASPLIT) issueA(kc + 2, st2);
            issueB(kc + 2, st2);
            CP_COMMIT();
        }

        const uint32_t base = sb + st * STG;
#pragma unroll
        for (int ks = 0; ks < 4; ks++) {
            uint32_t ah[4], al[4];
            uint32_t aAddr = base + (uint32_t)(aRowB * SKP + ks * 16 + aKoff) * 2;
            ldsm_x4(ah, aAddr);
            ldsm_x4(al, aAddr + AB);
#pragma unroll
            for (int p = 0; p < P; p++) {
                uint32_t bh[4], bl[4];
                uint32_t bAddr = base + 2 * AB +
                    (uint32_t)((bRowB + p * 16) * SKP + ks * 16 + bKoff) * 2;
                ldsm_x4(bh, bAddr);
                ldsm_x4(bl, bAddr + BB);
                mma16816(acc[p][0], ah, &bh[0]);
                mma16816(acc[p][1], ah, &bh[2]);
                mma16816(acc[p][0], ah, &bl[0]);
                mma16816(acc[p][1], ah, &bl[2]);
                mma16816(acc[p][0], al, &bh[0]);
                mma16816(acc[p][1], al, &bh[2]);
            }
        }
        if (++st == 3) st = 0;
    }
    __syncthreads();

    // ---- stage C to smem ----
    float* stage = (float*)smem;
#pragma unroll
    for (int p = 0; p < P; p++)
#pragma unroll
        for (int s = 0; s < 2; s++) {
            const float* c = acc[p][s];
            int m = warpM * 16 + (lid >> 2);
            int n = warpN * W + p * 16 + s * 8 + (lid & 3) * 2;
            stage[m * ST + n]           = c[0];
            stage[m * ST + n + 1]       = c[1];
            stage[(m + 8) * ST + n]     = c[2];
            stage[(m + 8) * ST + n + 1] = c[3];
        }
    __syncthreads();

    if (EPI == 0) {
#pragma unroll
        for (int i = 0; i < (ROWS * NCOLS) / 2048; i++) {
            int idx = i * 512 + tid; int m = idx >> 5, c4 = idx & 31;
            *(float4*)(po0 + (size_t)(row0 + m) * 128 + c4 * 4) =
                *(const float4*)(stage + m * ST + c4 * 4);
        }
    } else if (EPI == 1) {
        // trop (cols 32-63) and real (cols 64-95)
#pragma unroll
        for (int i = 0; i < ROWS / 32; i++) {
            int idx = i * 512 + tid; int m = idx >> 4, c4 = idx & 15;
            float4 v = *(const float4*)(stage + m * ST + 32 + c4 * 4);
            if (c4 < 8) *(float4*)(po0 + (size_t)(row0 + m) * 32 + c4 * 4) = v;
            else        *(float4*)(po1 + (size_t)(row0 + m) * 32 + (c4 - 8) * 4) = v;
        }
        // boolean bits: warp-cooperative exact fp32 fixup for near-zero logits
        if (tid < ROWS) {
            const int rbase = row0 + (wid << 5);
            unsigned bits = 0;
#pragma unroll 4
            for (int j = 0; j < 32; j++) {
                float v = stage[tid * ST + j];
                unsigned need = __ballot_sync(0xffffffffu, fabsf(v) < kFixTh);
                while (need) {
                    int src = __ffs(need) - 1;
                    need &= need - 1;
                    const float* xr = aF + (size_t)(rbase + src) * 1024;
                    const float* wr = Bfix + (size_t)j * 1024;
                    float s = 0.f;
#pragma unroll 8
                    for (int k = lid; k < 1024; k += 32)
                        s = fmaf(xr[k], wr[k], s);
#pragma unroll
                    for (int o = 16; o > 0; o >>= 1)
                        s += __shfl_xor_sync(0xffffffffu, s, o);
                    if (lid == src) v = s;
                }
                bits |= (v > 0.f ? 1u : 0u) << j;
            }
            po2[row0 + tid] = bits;
        }
    } else { // EPI == 2: split-bf16 transposed store vpT[(b*128+h)][m]
        const int b = row0 >> 10;
        const int m0 = row0 & 1023;
        const int h = tid & 127, q4 = tid >> 7;
        constexpr int MH = ROWS / 4;
        __nv_bfloat16* vh = (__nv_bfloat16*)po0 + ((size_t)b * 128 + h) * 1024 + m0 + q4 * MH;
        __nv_bfloat16* vl = (__nv_bfloat16*)po1 + ((size_t)b * 128 + h) * 1024 + m0 + q4 * MH;
#pragma unroll
        for (int mm = 0; mm < MH; mm += 4) {
            int mb = q4 * MH + mm;
            float4 v = make_float4(stage[(mb + 0) * ST + h], stage[(mb + 1) * ST + h],
                                   stage[(mb + 2) * ST + h], stage[(mb + 3) * ST + h]);
            uint2 H, L; split_pack(v, H, L);
            *(uint2*)(vh + mm) = H;
            *(uint2*)(vl + mm) = L;
        }
    }
}

// ================================================================
// weight prep — 32x32 smem tile transpose, fully coalesced both ways
// ================================================================
__global__ __launch_bounds__(256) void wprep_kernel(
    const float* __restrict__ Wqb, const float* __restrict__ Wqt, const float* __restrict__ Wqr,
    const float* __restrict__ Wkb, const float* __restrict__ Wkt, const float* __restrict__ Wkr,
    const float* __restrict__ Wv)
{
    __shared__ float t[32][36];
    const int tid = threadIdx.x;
    const int bid = blockIdx.x;

    const float* W; int stride, jin, dt, jout;
    float* oF; __nv_bfloat16 *oH, *oL;
    if (bid < 192) {
        int src = bid >> 5; dt = bid & 31;
        stride = 32; jin = 0;
        if (src == 0)      { W = Wqb; jout = 0;  oF = g_wqT; oH = g_wqTh; oL = g_wqTl; }
        else if (src == 1) { W = Wqt; jout = 32; oF = g_wqT; oH = g_wqTh; oL = g_wqTl; }
        else if (src == 2) { W = Wqr; jout = 64; oF = g_wqT; oH = g_wqTh; oL = g_wqTl; }
        else if (src == 3) { W = Wkb; jout = 0;  oF = g_wkT; oH = g_wkTh; oL = g_wkTl; }
        else if (src == 4) { W = Wkt; jout = 32; oF = g_wkT; oH = g_wkTh; oL = g_wkTl; }
        else               { W = Wkr; jout = 64; oF = g_wkT; oH = g_wkTh; oL = g_wkTl; }
    } else {
        int t2 = bid - 192; dt = t2 & 31; int jt = t2 >> 5;
        stride = 128; jin = jt * 32; jout = jt * 32;
        W = Wv; oF = nullptr; oH = g_wvTh; oL = g_wvTl;
    }

    {
        int r = tid >> 3, c4 = (tid & 7) * 4;
        float4 v = *(const float4*)(W + (size_t)(dt * 32 + r) * stride + jin + c4);
        *(float4*)&t[r][c4] = v;
    }
    __syncthreads();
    {
        int j = tid >> 3, dc = (tid & 7) * 4;
        float4 v = make_float4(t[dc + 0][j], t[dc + 1][j], t[dc + 2][j], t[dc + 3][j]);
        size_t off = (size_t)(jout + j) * 1024 + dt * 32 + dc;
        if (oF) *(float4*)(oF + off) = v;
        uint2 H, L; split_pack(v, H, L);
        *(uint2*)(oH + off) = H;
        *(uint2*)(oL + off) = L;
    }
}

// ================================================================
// Fused monoid scores — R11-proven 64x64 tile, 4x4/thread
// ================================================================
__global__ __launch_bounds__(256) void scores_kernel(
    const float* __restrict__ fw, const int* __restrict__ mask,
    float* __restrict__ attn)
{
    __shared__ float qt[64][32];
    __shared__ float qr[64][32];
    __shared__ float kts[32][68];
    __shared__ float krs[32][68];
    __shared__ unsigned qb_s[64];
    __shared__ unsigned kb_s[64];

    const int tid = threadIdx.x;
    const int b  = blockIdx.z;
    const int n0 = blockIdx.y * 64;
    const int m0 = blockIdx.x * 64;
    const int qbase = b * Nc + n0;
    const int kbase = b * Mc + m0;

#pragma unroll
    for (int l = 0; l < 2; l++) {
        int idx = tid + l * 256;
        int r = idx >> 3, c = (idx & 7) * 4;
        *(float4*)&qt[r][c] = *(const float4*)(g_qt + (size_t)(qbase + r) * MBITS + c);
        *(float4*)&qr[r][c] = *(const float4*)(g_qr + (size_t)(qbase + r) * MBITS + c);
    }
#pragma unroll
    for (int l = 0; l < 8; l++) {
        int idx = tid + l * 256;
        int r = idx >> 5, d = idx & 31;
        kts[d][r] = g_kt[(size_t)(kbase + r) * MBITS + d];
        krs[d][r] = g_kr[(size_t)(kbase + r) * MBITS + d];
    }
    if (tid < 64)            qb_s[tid]       = g_qb[qbase + tid];
    else if (tid < 128)      kb_s[tid - 64]  = g_kb[kbase + tid - 64];
    __syncthreads();

    const int tn0 = (tid >> 4) * 4;
    const int tm0 = (tid & 15) * 4;

    float tAcc[4][4];
    unsigned long long rA2[4][2];
#pragma unroll
    for (int i = 0; i < 4; i++) {
#pragma unroll
        for (int j = 0; j < 4; j++) tAcc[i][j] = NEG_INF;
        rA2[i][0] = 0ull; rA2[i][1] = 0ull;
    }

#pragma unroll
    for (int d0 = 0; d0 < 32; d0 += 4) {
        float qtl[4][4], qrl[4][4];
#pragma unroll
        for (int i = 0; i < 4; i++) {
            float4 t = *(float4*)&qt[tn0 + i][d0];
            float4 r = *(float4*)&qr[tn0 + i][d0];
            qtl[i][0] = t.x; qtl[i][1] = t.y; qtl[i][2] = t.z; qtl[i][3] = t.w;
            qrl[i][0] = r.x; qrl[i][1] = r.y; qrl[i][2] = r.z; qrl[i][3] = r.w;
        }
#pragma unroll
        for (int dd = 0; dd < 4; dd++) {
            ulonglong2 kt2 = *(const ulonglong2*)&kts[d0 + dd][tm0];
            ulonglong2 kr2 = *(const ulonglong2*)&krs[d0 + dd][tm0];
#pragma unroll
            for (int i = 0; i < 4; i++) {
                unsigned long long qtd2 = bcast2(qtl[i][dd]);
                unsigned long long qrd2 = bcast2(qrl[i][dd]);
                float2 s0 = unpack2(add2(qtd2, kt2.x));
                float2 s1 = unpack2(add2(qtd2, kt2.y));
                tAcc[i][0] = fmaxf(tAcc[i][0], s0.x);
                tAcc[i][1] = fmaxf(tAcc[i][1], s0.y);
                tAcc[i][2] = fmaxf(tAcc[i][2], s1.x);
                tAcc[i][3] = fmaxf(tAcc[i][3], s1.y);
                fma2(rA2[i][0], qrd2, kr2.x);
                fma2(rA2[i][1], qrd2, kr2.y);
            }
        }
    }

    float f0 = fw[0], f1 = fw[1], f2 = fw[2];
    float fm = fmaxf(f0, fmaxf(f1, f2));
    float e0 = __expf(f0 - fm), e1 = __expf(f1 - fm), e2 = __expf(f2 - fm);
    float inv = 1.f / (e0 + e1 + e2);
    float w0 = e0 * inv, w1 = e1 * inv, w2 = e2 * inv;

    unsigned qbv[4], kbv[4];
#pragma unroll
    for (int i = 0; i < 4; i++) qbv[i] = qb_s[tn0 + i];
#pragma unroll
    for (int j = 0; j < 4; j++) kbv[j] = kb_s[tm0 + j];

#pragma unroll
    for (int i = 0; i < 4; i++) {
        float2 r01 = unpack2(rA2[i][0]);
        float2 r23 = unpack2(rA2[i][1]);
        size_t off = ((size_t)b * Nc + n0 + tn0 + i) * Mc + m0 + tm0;
        int4 mk = *(const int4*)(mask + off);
        float s0 = (w0 * (float)(32 - __popc(qbv[i] ^ kbv[0])) + w1 * tAcc[i][0] + w2 * r01.x) * kScale;
        float s1 = (w0 * (float)(32 - __popc(qbv[i] ^ kbv[1])) + w1 * tAcc[i][1] + w2 * r01.y) * kScale;
        float s2 = (w0 * (float)(32 - __popc(qbv[i] ^ kbv[2])) + w1 * tAcc[i][2] + w2 * r23.x) * kScale;
        float s3 = (w0 * (float)(32 - __popc(qbv[i] ^ kbv[3])) + w1 * tAcc[i][3] + w2 * r23.y) * kScale;
        float4 o;
        o.x = (mk.x == 0) ? NEG_INF : s0;
        o.y = (mk.y == 0) ? NEG_INF : s1;
        o.z = (mk.z == 0) ? NEG_INF : s2;
        o.w = (mk.w == 0) ? NEG_INF : s3;
        *(float4*)(attn + off) = o;
    }
}

// ================================================================
// Row softmax over M=1024 in place
// ================================================================
__global__ __launch_bounds__(256) void softmax_kernel(float* __restrict__ attn)
{
    __shared__ float red[8];
    const size_t row = blockIdx.x;
    float* p = attn + row * (size_t)Mc;
    const int tid = threadIdx.x;
    const int lane = tid & 31, wid = tid >> 5;

    float4 v = *(float4*)(p + tid * 4);
    float m = fmaxf(fmaxf(v.x, v.y), fmaxf(v.z, v.w));
#pragma unroll
    for (int o = 16; o > 0; o >>= 1) m = fmaxf(m, __shfl_xor_sync(0xffffffffu, m, o));
    if (lane == 0) red[wid] = m;
    __syncthreads();
    float bm = fmaxf(fmaxf(fmaxf(red[0], red[1]), fmaxf(red[2], red[3])),
                     fmaxf(fmaxf(red[4], red[5]), fmaxf(red[6], red[7])));
    __syncthreads();

    float4 e;
    e.x = __expf(v.x - bm); e.y = __expf(v.y - bm);
    e.z = __expf(v.z - bm); e.w = __expf(v.w - bm);
    float s = e.x + e.y + e.z + e.w;
#pragma unroll
    for (int o = 16; o > 0; o >>= 1) s += __shfl_xor_sync(0xffffffffu, s, o);
    if (lane == 0) red[wid] = s;
    __syncthreads();
    float ts = red[0] + red[1] + red[2] + red[3] + red[4] + red[5] + red[6] + red[7];
    float invs = 1.f / ts;
    e.x *= invs; e.y *= invs; e.z *= invs; e.w *= invs;
    *(float4*)(p + tid * 4) = e;
}

// ================================================================
extern "C" void kernel_launch(void* const* d_in, const int* in_sizes, int n_in,
                              void* d_out, int out_size)
{
    const float* Q    = (const float*)d_in[0];
    const float* K    = (const float*)d_in[1];
    const float* V    = (const float*)d_in[2];
    const float* Wqb  = (const float*)d_in[3];
    const float* Wkb  = (const float*)d_in[4];
    const float* Wqt  = (const float*)d_in[5];
    const float* Wkt  = (const float*)d_in[6];
    const float* Wqr  = (const float*)d_in[7];
    const float* Wkr  = (const float*)d_in[8];
    const float* Wv   = (const float*)d_in[9];
    const float* fw   = (const float*)d_in[10];
    const int*   mask = (const int*)d_in[11];

    float* out  = (float*)d_out;                         // [B,N,128]
    float* attn = (float*)d_out + (size_t)Bc * Nc * Hc;  // [B,N,M]

    float *qt, *qr, *kt, *kr, *wqT, *wkT;
    unsigned *qb, *kb;
    __nv_bfloat16 *wqTh, *wqTl, *wkTh, *wkTl, *wvTh, *wvTl;
    __nv_bfloat16 *vpTh, *vpTl;
    cudaGetSymbolAddress((void**)&qt, g_qt);
    cudaGetSymbolAddress((void**)&qr, g_qr);
    cudaGetSymbolAddress((void**)&qb, g_qb);
    cudaGetSymbolAddress((void**)&kt, g_kt);
    cudaGetSymbolAddress((void**)&kr, g_kr);
    cudaGetSymbolAddress((void**)&kb, g_kb);
    cudaGetSymbolAddress((void**)&wqT, g_wqT);
    cudaGetSymbolAddress((void**)&wkT, g_wkT);
    cudaGetSymbolAddress((void**)&wqTh, g_wqTh);
    cudaGetSymbolAddress((void**)&wqTl, g_wqTl);
    cudaGetSymbolAddress((void**)&wkTh, g_wkTh);
    cudaGetSymbolAddress((void**)&wkTl, g_wkTl);
    cudaGetSymbolAddress((void**)&wvTh, g_wvTh);
    cudaGetSymbolAddress((void**)&wvTl, g_wvTl);
    cudaGetSymbolAddress((void**)&vpTh, g_vpTh);
    cudaGetSymbolAddress((void**)&vpTl, g_vpTl);

    const int SMEM_PROJ = 3 * (128 * 144 * 2 + 96 * 144 * 2);   // 193536
    const int SMEM_VO   = 3 * (64 * 144 * 2 + 128 * 144 * 2);   // 165888
    cudaFuncSetAttribute(lgemm_kernel<96, 1, 8, 1>,  cudaFuncAttributeMaxDynamicSharedMemorySize, SMEM_PROJ);
    cudaFuncSetAttribute(lgemm_kernel<128, 2, 4, 1>, cudaFuncAttributeMaxDynamicSharedMemorySize, SMEM_VO);
    cudaFuncSetAttribute(lgemm_kernel<128, 0, 4, 1>, cudaFuncAttributeMaxDynamicSharedMemorySize, SMEM_VO);

    // side stream (created once, outside capture; correctness call precedes
    // graph capture)
    static cudaStream_t s2 = nullptr;
    static cudaEvent_t evF = nullptr, evJ = nullptr;
    if (s2 == nullptr) {
        cudaStreamCreateWithFlags(&s2, cudaStreamNonBlocking);
        cudaEventCreateWithFlags(&evF, cudaEventDisableTiming);
        cudaEventCreateWithFlags(&evJ, cudaEventDisableTiming);
    }

    // 0: weight prep (coalesced tile transpose)
    wprep_kernel<<<320, 256>>>(Wqb, Wqt, Wqr, Wkb, Wkt, Wkr, Wv);

    // 1: Q + K projections (tensor-heavy, runs alone)
    lgemm_kernel<96, 1, 8, 1><<<128, 512, SMEM_PROJ>>>(
        Q, nullptr, nullptr, wqTh, wqTl, wqT, qt, qr, qb,
        K, wkTh, wkTl, wkT, kt, kr, kb, 64, 0);

    // fork AFTER proj: VP (tensor-heavy) overlaps scores+softmax (tensor-idle)
    cudaEventRecord(evF, 0);
    cudaStreamWaitEvent(s2, evF, 0);
    lgemm_kernel<128, 2, 4, 1><<<128, 512, SMEM_VO, s2>>>(
        V, nullptr, nullptr, wvTh, wvTl, nullptr, (float*)vpTh, (float*)vpTl, nullptr,
        nullptr, nullptr, nullptr, nullptr, nullptr, nullptr, nullptr, 128, 0);

    // main: fused monoid scores (tensor=0%) — VP fills the tensor pipe
    scores_kernel<<<dim3(16, 16, 8), 256>>>(fw, mask, attn);

    // main: softmax (in place, DRAM-bound)
    softmax_kernel<<<Bc * Nc, 256>>>(attn);

    // join: out needs VP + softmax
    cudaEventRecord(evJ, s2);
    cudaStreamWaitEvent(0, evJ, 0);
    lgemm_kernel<128, 0, 4, 1><<<128, 512, SMEM_VO>>>(
        attn, nullptr, nullptr, vpTh, vpTl, nullptr, out, nullptr, nullptr,
        nullptr, nullptr, nullptr, nullptr, nullptr, nullptr, nullptr, 128, 1);
}